// round 6
// baseline (speedup 1.0000x reference)
#include <cuda_runtime.h>
#include <stdint.h>

#define B       8
#define NH      778
#define VOBJ    40000
#define NTOT    (B * NH)          // 6224
#define THREADS 160               // 5 warps
#define HREG    5                 // 160*5 = 800 >= 778 (2.8% waste)
#define OSLICES 148               // 148*8 = 1184 blocks = exactly 8 per SM, one wave
#define OSLICE  272               // 272*147 + 16 = 40000; tail padded by clamping
#define NPAIRS  136               // COMPILE-TIME trip count

__constant__ int c_contact_idx[10] = {745, 317, 444, 556, 673, 95, 182, 234, 279, 320};

// per-slice partial d^2: [OSLICES][B][NH] — fully rewritten each launch
__device__ float g_part[OSLICES * NTOT];
// stage-A per-block partials
__device__ float g_red_f[25 * 3];
__device__ int   g_red_i[25 * 2];

__device__ __forceinline__ unsigned long long pack2(float a, float b) {
    unsigned long long r;
    asm("mov.b64 %0, {%1, %2};" : "=l"(r) : "f"(a), "f"(b));
    return r;
}
__device__ __forceinline__ unsigned long long fma2(unsigned long long a,
                                                   unsigned long long b,
                                                   unsigned long long c) {
    unsigned long long d;
    asm("fma.rn.f32x2 %0, %1, %2, %3;" : "=l"(d) : "l"(a), "l"(b), "l"(c));
    return d;
}
__device__ __forceinline__ void unpack2(unsigned long long v, float& lo, float& hi) {
    asm("mov.b64 {%0, %1}, %2;" : "=f"(lo), "=f"(hi) : "l"(v));
}

__global__ __launch_bounds__(THREADS, 8) void mindist_kernel(
    const float* __restrict__ hand, const float* __restrict__ obj)
{
    const int b     = blockIdx.z;
    const int slice = blockIdx.y;
    const int t     = threadIdx.x;

    // each thread owns HREG hand verts: h = t + k*THREADS (coalesced loads)
    unsigned long long axx[HREG], ayy[HREG], azz[HREG];
    float asq[HREG];
    #pragma unroll
    for (int k = 0; k < HREG; k++) {
        int h  = t + k * THREADS;
        int hc = (h < NH) ? h : 0;          // clamp: spare lanes recompute vert 0
        const float* hp = hand + ((size_t)b * NH + hc) * 3;
        float ax = hp[0], ay = hp[1], az = hp[2];
        asq[k] = fmaf(ax, ax, fmaf(ay, ay, az * az));
        axx[k] = pack2(ax, ax);
        ayy[k] = pack2(ay, ay);
        azz[k] = pack2(az, az);
    }

    // packed-pair SoA: shA[p]={(-2x0,-2x1),(-2y0,-2y1)}, shB[p]={(-2z0,-2z1),(bsq0,bsq1)}
    __shared__ ulonglong2 shA[NPAIRS];
    __shared__ ulonglong2 shB[NPAIRS];

    const int o0 = slice * OSLICE;

    // single-round tile fill; pad-by-clamp (duplicate points never change a min)
    if (t < NPAIRS) {
        int pidx = o0 + t * 2;
        pidx = (pidx <= VOBJ - 2) ? pidx : (VOBJ - 2);
        const float* op = obj + ((size_t)b * VOBJ + pidx) * 3;
        float2 p01 = *(const float2*)(op + 0);   // x0 y0
        float2 p23 = *(const float2*)(op + 2);   // z0 x1
        float2 p45 = *(const float2*)(op + 4);   // y1 z1
        float x0 = p01.x, y0 = p01.y, z0 = p23.x;
        float x1 = p23.y, y1 = p45.x, z1 = p45.y;
        float w0 = fmaf(x0, x0, fmaf(y0, y0, z0 * z0));
        float w1 = fmaf(x1, x1, fmaf(y1, y1, z1 * z1));
        ulonglong2 A, Bv;
        A.x  = pack2(-2.f * x0, -2.f * x1);
        A.y  = pack2(-2.f * y0, -2.f * y1);
        Bv.x = pack2(-2.f * z0, -2.f * z1);
        Bv.y = pack2(w0, w1);
        shA[t] = A;
        shB[t] = Bv;
    }
    __syncthreads();

    float m0[HREG], m1[HREG];
    #pragma unroll
    for (int k = 0; k < HREG; k++) { m0[k] = 3.4e38f; m1[k] = 3.4e38f; }

    // compile-time trip count (136 = 34*4) -> real unroll + software pipelining
    #pragma unroll 4
    for (int p = 0; p < NPAIRS; ++p) {
        ulonglong2 A  = shA[p];
        ulonglong2 Bv = shB[p];
        #pragma unroll
        for (int k = 0; k < HREG; k++) {
            unsigned long long e =
                fma2(A.x, axx[k], fma2(A.y, ayy[k], fma2(Bv.x, azz[k], Bv.y)));
            float e0, e1;
            unpack2(e, e0, e1);
            m0[k] = fminf(m0[k], e0);
            m1[k] = fminf(m1[k], e1);
        }
    }

    float* dst = g_part + (size_t)(slice * B + b) * NH;
    #pragma unroll
    for (int k = 0; k < HREG; k++) {
        int h = t + k * THREADS;
        if (h < NH) dst[h] = asq[k] + fminf(m0[k], m1[k]);   // d^2 (clamped later)
    }
}

// stage A: 25 blocks x 256 threads — slice-min per vertex + per-block partial sums
__global__ __launch_bounds__(256) void reduceA_kernel()
{
    const int tid = threadIdx.x;
    const int i   = blockIdx.x * 256 + tid;

    float sum_d = 0.f, pen_sum = 0.f, att_sum = 0.f;
    int   pen_cnt = 0, att_cnt = 0;

    if (i < NTOT) {
        // 4 independent accumulators -> MLP 4 against L2 latency
        float mn0 = 3.4e38f, mn1 = 3.4e38f, mn2 = 3.4e38f, mn3 = 3.4e38f;
        #pragma unroll 4
        for (int s = 0; s < OSLICES; s += 4) {
            mn0 = fminf(mn0, g_part[(size_t)(s + 0) * NTOT + i]);
            mn1 = fminf(mn1, g_part[(size_t)(s + 1) * NTOT + i]);
            mn2 = fminf(mn2, g_part[(size_t)(s + 2) * NTOT + i]);
            mn3 = fminf(mn3, g_part[(size_t)(s + 3) * NTOT + i]);
        }
        float mn = fminf(fminf(mn0, mn1), fminf(mn2, mn3));
        float d = sqrtf(fmaxf(mn, 0.f));
        sum_d = d;
        if (d < 0.005f) {
            float tt = 0.005f - d;
            pen_sum = tt * tt;
            pen_cnt = 1;
        }
        int h = i % NH;
        bool is_contact = false;
        #pragma unroll
        for (int j = 0; j < 10; j++) is_contact |= (h == c_contact_idx[j]);
        if (is_contact && d > 0.005f && d < 0.01f) {
            att_sum = d * d;
            att_cnt = 1;
        }
    }

    __shared__ float s_f[3][8];
    __shared__ int   s_i[2][8];
    const unsigned FULL = 0xffffffffu;
    for (int off = 16; off > 0; off >>= 1) {
        sum_d   += __shfl_down_sync(FULL, sum_d,   off);
        pen_sum += __shfl_down_sync(FULL, pen_sum, off);
        att_sum += __shfl_down_sync(FULL, att_sum, off);
        pen_cnt += __shfl_down_sync(FULL, pen_cnt, off);
        att_cnt += __shfl_down_sync(FULL, att_cnt, off);
    }
    int wid = tid >> 5, lid = tid & 31;
    if (lid == 0) {
        s_f[0][wid] = sum_d; s_f[1][wid] = pen_sum; s_f[2][wid] = att_sum;
        s_i[0][wid] = pen_cnt; s_i[1][wid] = att_cnt;
    }
    __syncthreads();
    if (tid == 0) {
        float a = 0.f, c = 0.f, e = 0.f;
        int   p = 0, q = 0;
        #pragma unroll
        for (int w = 0; w < 8; w++) {
            a += s_f[0][w]; c += s_f[1][w]; e += s_f[2][w];
            p += s_i[0][w]; q += s_i[1][w];
        }
        g_red_f[blockIdx.x * 3 + 0] = a;
        g_red_f[blockIdx.x * 3 + 1] = c;
        g_red_f[blockIdx.x * 3 + 2] = e;
        g_red_i[blockIdx.x * 2 + 0] = p;
        g_red_i[blockIdx.x * 2 + 1] = q;
    }
}

// stage B: one warp combines the 25 block partials
__global__ void reduceB_kernel(float* __restrict__ out)
{
    const int lid = threadIdx.x;
    float sum_d = 0.f, pen_sum = 0.f, att_sum = 0.f;
    int   pen_cnt = 0, att_cnt = 0;
    if (lid < 25) {
        sum_d   = g_red_f[lid * 3 + 0];
        pen_sum = g_red_f[lid * 3 + 1];
        att_sum = g_red_f[lid * 3 + 2];
        pen_cnt = g_red_i[lid * 2 + 0];
        att_cnt = g_red_i[lid * 2 + 1];
    }
    const unsigned FULL = 0xffffffffu;
    for (int off = 16; off > 0; off >>= 1) {
        sum_d   += __shfl_down_sync(FULL, sum_d,   off);
        pen_sum += __shfl_down_sync(FULL, pen_sum, off);
        att_sum += __shfl_down_sync(FULL, att_sum, off);
        pen_cnt += __shfl_down_sync(FULL, pen_cnt, off);
        att_cnt += __shfl_down_sync(FULL, att_cnt, off);
    }
    if (lid == 0) {
        float pen_loss = (pen_cnt > 0) ? pen_sum / (float)pen_cnt : 0.f;
        float att_loss = (att_cnt > 0) ? att_sum / (float)att_cnt : 0.f;
        out[0] = 100.f * pen_loss + 10.f * att_loss;
        out[1] = pen_loss;
        out[2] = att_loss;
        out[3] = sum_d / (float)NTOT;
        out[4] = (float)att_cnt;   // num_contacts
        out[5] = (float)pen_cnt;   // num_penetrations
    }
}

extern "C" void kernel_launch(void* const* d_in, const int* in_sizes, int n_in,
                              void* d_out, int out_size)
{
    const float* hand = (const float*)d_in[0];  // [8, 778, 3] f32
    const float* obj  = (const float*)d_in[1];  // [8, 40000, 3] f32
    float* out = (float*)d_out;

    dim3 grid(1, OSLICES, B);                   // 1184 blocks = 8/SM, one wave
    mindist_kernel<<<grid, THREADS>>>(hand, obj);
    reduceA_kernel<<<25, 256>>>();
    reduceB_kernel<<<1, 32>>>(out);
    (void)in_sizes; (void)n_in; (void)out_size;
}